// round 10
// baseline (speedup 1.0000x reference)
#include <cuda_runtime.h>
#include <cuda_bf16.h>
#include <cuda_fp16.h>
#include <cstdint>

#define MAXN 100000
#define MAXE 1600000
#define HID 128
#define CLS 40

// ---------------- scratch (static device memory, no allocations) ----------------
__device__ int      g_ideg_src[MAXN];
__device__ int      g_ideg_dst[MAXN];
__device__ float    g_csrc[MAXN];
__device__ float    g_cdst[MAXN];
__device__ int      g_roff[MAXN + 1];
__device__ int      g_cursor[MAXN];
__device__ int      g_bsums[128];
__device__ int      g_csr[MAXE];
__device__ __half   g_tmp [(size_t)MAXN * HID];     // GEMM output, fp16
__device__ __half   g_hbuf[(size_t)MAXN * HID];     // layer-1 activations, fp16
// W pre-split + TRANSPOSED: per 32-k chunk: [n 128][kpair 16] u32 (bf16x2)
__device__ uint32_t g_whi0[16384], g_wlo0[16384];   // W0: 8 chunks x 2048
__device__ uint32_t g_whi1[8192],  g_wlo1[8192];    // W1: 4 chunks x 2048

// ---------------- utilities ----------------
__global__ void zero_int2_kernel(int* __restrict__ a, int* __restrict__ b, int n) {
    int i = blockIdx.x * blockDim.x + threadIdx.x;
    if (i < n) { a[i] = 0; b[i] = 0; }
}

__global__ void degree_kernel(const int* __restrict__ src, const int* __restrict__ dst, int e) {
    int i = blockIdx.x * blockDim.x + threadIdx.x;
    if (i < e) {
        atomicAdd(&g_ideg_src[src[i]], 1);
        atomicAdd(&g_ideg_dst[dst[i]], 1);
    }
}

// ---------------- 3-phase exclusive scan of in-degrees -> CSR row offsets ----------------
__global__ void scan1_kernel(const int* __restrict__ deg, int* __restrict__ out,
                             int* __restrict__ bsums, int n) {
    __shared__ int sm[1024];
    int i = blockIdx.x * 1024 + threadIdx.x;
    int v = (i < n) ? deg[i] : 0;
    sm[threadIdx.x] = v;
    __syncthreads();
    for (int off = 1; off < 1024; off <<= 1) {
        int t = (threadIdx.x >= off) ? sm[threadIdx.x - off] : 0;
        __syncthreads();
        sm[threadIdx.x] += t;
        __syncthreads();
    }
    if (i < n) out[i] = sm[threadIdx.x] - v;
    if (threadIdx.x == 1023) bsums[blockIdx.x] = sm[1023];
}

__global__ void scan2_kernel(int* __restrict__ bsums, int nb) {
    __shared__ int sm[128];
    int t = threadIdx.x;
    int v = (t < nb) ? bsums[t] : 0;
    sm[t] = v;
    __syncthreads();
    for (int off = 1; off < 128; off <<= 1) {
        int u = (t >= off) ? sm[t - off] : 0;
        __syncthreads();
        sm[t] += u;
        __syncthreads();
    }
    if (t < nb) bsums[t] = sm[t] - v;
}

__global__ void scan3_kernel(int* __restrict__ roff, int* __restrict__ cursor,
                             const int* __restrict__ bsums, int n, int e) {
    int i = blockIdx.x * blockDim.x + threadIdx.x;
    if (i < n) {
        int v = roff[i] + bsums[i >> 10];
        roff[i] = v;
        cursor[i] = v;
        g_csrc[i] = rsqrtf(fmaxf((float)g_ideg_src[i], 1.f));
        g_cdst[i] = rsqrtf(fmaxf((float)g_ideg_dst[i], 1.f));
    }
    if (i == 0) roff[n] = e;
}

__global__ void csr_fill_kernel(const int* __restrict__ src, const int* __restrict__ dst,
                                int* __restrict__ cursor, int* __restrict__ csr, int e) {
    int i = blockIdx.x * blockDim.x + threadIdx.x;
    if (i < e) {
        int d = dst[i];
        int pos = atomicAdd(&cursor[d], 1);
        csr[pos] = src[i];
    }
}

// ---------------- bf16 split helpers ----------------
__device__ __forceinline__ void split2_pack(float x, float y, uint32_t& hi, uint32_t& lo) {
    __nv_bfloat16 hx = __float2bfloat16(x);
    __nv_bfloat16 hy = __float2bfloat16(y);
    float rx = x - __bfloat162float(hx);
    float ry = y - __bfloat162float(hy);
    __nv_bfloat162 h2 = __halves2bfloat162(hx, hy);
    __nv_bfloat162 l2 = __floats2bfloat162_rn(rx, ry);
    hi = *reinterpret_cast<uint32_t*>(&h2);
    lo = *reinterpret_cast<uint32_t*>(&l2);
}

// W[K,128] fp32 -> per 32-k chunk transposed [n][kpair(16)] bf16x2 hi/lo
__global__ void wsplit_kernel(const float* __restrict__ W, uint32_t* __restrict__ whi,
                              uint32_t* __restrict__ wlo, int kpairs) {
    int idx = blockIdx.x * blockDim.x + threadIdx.x;   // (kp, n)
    if (idx < kpairs * 128) {
        int kp = idx >> 7, n = idx & 127;
        float x = W[(size_t)(2 * kp) * 128 + n];
        float y = W[(size_t)(2 * kp + 1) * 128 + n];
        uint32_t h, l;
        split2_pack(x, y, h, l);
        int ch = kp >> 4, kpl = kp & 15;
        uint32_t o = (uint32_t)ch * 2048 + (uint32_t)n * 16 + kpl;
        whi[o] = h;
        wlo[o] = l;
    }
}

#define MMA_BF16(d, a, b0v, b1v)                                                  \
    asm volatile("mma.sync.aligned.m16n8k16.row.col.f32.bf16.bf16.f32 "           \
                 "{%0,%1,%2,%3}, {%4,%5,%6,%7}, {%8,%9}, {%0,%1,%2,%3};"          \
                 : "+f"((d)[0]), "+f"((d)[1]), "+f"((d)[2]), "+f"((d)[3])         \
                 : "r"((a)[0]), "r"((a)[1]), "r"((a)[2]), "r"((a)[3]),            \
                   "r"(b0v), "r"(b1v));

#define LDSM4(r, addr)                                                             \
    asm volatile("ldmatrix.sync.aligned.m8n8.x4.shared.b16 {%0,%1,%2,%3}, [%4];"  \
                 : "=r"((r)[0]), "=r"((r)[1]), "=r"((r)[2]), "=r"((r)[3])         \
                 : "r"(addr))

#define TS 20            // u32 stride per row (16 kpairs + pad) — conflict-free for LDSM
#define TBUF 2560        // 128 rows * TS
#define GEMM_SMEM (8 * TBUF * 4)   // AsHi/AsLo/BsHi/BsLo x double buffer = 81920 B

#define CP_ASYNC16(dst_u32, src_ptr)                                              \
    asm volatile("cp.async.cg.shared.global [%0], [%1], 16;"                      \
                 :: "r"(dst_u32), "l"(src_ptr))
#define CP_COMMIT() asm volatile("cp.async.commit_group;" ::: "memory")
#define CP_WAIT0()  asm volatile("cp.async.wait_group 0;"  ::: "memory")

__device__ __forceinline__ float4 ld4(const float* A, size_t off) {
    return __ldg(reinterpret_cast<const float4*>(A + off));
}
__device__ __forceinline__ float4 ld4(const __half* A, size_t off) {
    uint2 u = __ldg(reinterpret_cast<const uint2*>(A + off));
    float2 a = __half22float2(*reinterpret_cast<__half2*>(&u.x));
    float2 b = __half22float2(*reinterpret_cast<__half2*>(&u.y));
    return make_float4(a.x, a.y, b.x, b.y);
}

// ---------------- ldmatrix double-buffered bf16x3 HMMA GEMM: C(fp16) = A[M,K] @ W
template<typename TA>
__global__ __launch_bounds__(256, 2)
void gemm_bf16_kernel(const TA* __restrict__ A, const uint32_t* __restrict__ whi,
                      const uint32_t* __restrict__ wlo, __half* __restrict__ C,
                      int M, int K) {
    extern __shared__ uint32_t smem[];
    uint32_t* AsHi = smem;               // [2][TBUF]
    uint32_t* AsLo = smem + 2 * TBUF;
    uint32_t* BsHi = smem + 4 * TBUF;    // [2][TBUF] transposed [n][kp]
    uint32_t* BsLo = smem + 6 * TBUF;

    const uint32_t aHiB = (uint32_t)__cvta_generic_to_shared(AsHi);
    const uint32_t aLoB = (uint32_t)__cvta_generic_to_shared(AsLo);
    const uint32_t bHiB = (uint32_t)__cvta_generic_to_shared(BsHi);
    const uint32_t bLoB = (uint32_t)__cvta_generic_to_shared(BsLo);

    const int tid  = threadIdx.x;
    const int warp = tid >> 5, lane = tid & 31;
    const int wm   = warp >> 1, wn = warp & 1;
    const int gid  = lane >> 2, tig = lane & 3;
    const int m0   = blockIdx.x * 128;
    const int nIter = K >> 5;

    // ldmatrix lane->address components
    const int aRow = (lane & 7) + ((lane >> 3) & 1) * 8;   // + rb
    const int aCh  = (lane >> 4) * 4;                      // + kkp
    const int bRow = (lane & 7) + (lane >> 4) * 8;         // + nb
    const int bCh  = ((lane >> 3) & 1) * 4;                // + kkp

    float acc[2][8][4];
#pragma unroll
    for (int mt = 0; mt < 2; mt++)
#pragma unroll
        for (int nt = 0; nt < 8; nt++)
#pragma unroll
            for (int j = 0; j < 4; j++) acc[mt][nt][j] = 0.f;

    float4 aReg[4];

#define LD_A(k0)                                                                   \
    {                                                                              \
        _Pragma("unroll")                                                          \
        for (int l = 0; l < 4; l++) {                                              \
            int idx = tid + l * 256;                                               \
            int r = idx >> 3, c4 = idx & 7;                                        \
            aReg[l] = (m0 + r < M)                                                 \
                ? ld4(A, (size_t)(m0 + r) * K + (k0) + (c4 << 2))                  \
                : make_float4(0.f, 0.f, 0.f, 0.f);                                 \
        }                                                                          \
    }

#define ST_A(dstHi, dstLo)                                                         \
    {                                                                              \
        _Pragma("unroll")                                                          \
        for (int l = 0; l < 4; l++) {                                              \
            int idx = tid + l * 256;                                               \
            int r = idx >> 3, c4 = idx & 7;                                        \
            uint32_t h0, l0, h1, l1;                                               \
            split2_pack(aReg[l].x, aReg[l].y, h0, l0);                             \
            split2_pack(aReg[l].z, aReg[l].w, h1, l1);                             \
            (dstHi)[r * TS + 2 * c4]     = h0;                                     \
            (dstHi)[r * TS + 2 * c4 + 1] = h1;                                     \
            (dstLo)[r * TS + 2 * c4]     = l0;                                     \
            (dstLo)[r * TS + 2 * c4 + 1] = l1;                                     \
        }                                                                          \
    }

    // B copy: 512 x 16B per hi/lo; global [ch][n][16kp] -> smem [n][TS]
#define CP_B(ch, dstHiOff, dstLoOff)                                               \
    {                                                                              \
        _Pragma("unroll")                                                          \
        for (int l = 0; l < 2; l++) {                                              \
            int idx = tid + l * 256;           /* 0..511: (row, 16B chunk) */      \
            int row = idx >> 2, c4 = idx & 3;                                      \
            uint32_t duo = (uint32_t)((row * TS + c4 * 4) * 4);                    \
            CP_ASYNC16(bHiB + (dstHiOff) + duo, whi + (size_t)(ch) * 2048 + idx * 4); \
            CP_ASYNC16(bLoB + (dstLoOff) + duo, wlo + (size_t)(ch) * 2048 + idx * 4); \
        }                                                                          \
    }

    // prologue
    CP_B(0, 0, 0);
    CP_COMMIT();
    LD_A(0);
    ST_A(AsHi, AsLo);
    CP_WAIT0();
    __syncthreads();

    for (int it = 0; it < nIter; it++) {
        const int cur = it & 1, nxt = cur ^ 1;
        const bool more = (it + 1 < nIter);
        if (more) {
            LD_A((it + 1) << 5);
            CP_B(it + 1, nxt * TBUF * 4, nxt * TBUF * 4);
            CP_COMMIT();
        }

        const uint32_t aHiC = aHiB + cur * TBUF * 4;
        const uint32_t aLoC = aLoB + cur * TBUF * 4;
        const uint32_t bHiC = bHiB + cur * TBUF * 4;
        const uint32_t bLoC = bLoB + cur * TBUF * 4;

#pragma unroll
        for (int kkp = 0; kkp < 16; kkp += 8) {
            uint32_t ah[2][4], al[2][4];
#pragma unroll
            for (int mt = 0; mt < 2; mt++) {
                uint32_t off = (uint32_t)(((wm * 32 + mt * 16 + aRow) * TS + kkp + aCh) * 4);
                LDSM4(ah[mt], aHiC + off);
                LDSM4(al[mt], aLoC + off);
            }
#pragma unroll
            for (int ntp = 0; ntp < 4; ntp++) {
                uint32_t boff = (uint32_t)(((wn * 64 + ntp * 16 + bRow) * TS + kkp + bCh) * 4);
                uint32_t bh[4], bl[4];
                LDSM4(bh, bHiC + boff);
                LDSM4(bl, bLoC + boff);
#pragma unroll
                for (int s = 0; s < 2; s++) {
                    const int nt = 2 * ntp + s;
#pragma unroll
                    for (int mt = 0; mt < 2; mt++) {
                        MMA_BF16(acc[mt][nt], ah[mt], bh[2 * s], bh[2 * s + 1]);
                        MMA_BF16(acc[mt][nt], al[mt], bh[2 * s], bh[2 * s + 1]);
                        MMA_BF16(acc[mt][nt], ah[mt], bl[2 * s], bl[2 * s + 1]);
                    }
                }
            }
        }

        if (more) {
            ST_A(AsHi + nxt * TBUF, AsLo + nxt * TBUF);
            CP_WAIT0();
        }
        __syncthreads();
    }

    // epilogue: store fp16 pairs (c_src applied later in SpMM gather)
#pragma unroll
    for (int mt = 0; mt < 2; mt++) {
        int r0 = m0 + wm * 32 + mt * 16 + gid;
        int r1 = r0 + 8;
#pragma unroll
        for (int nt = 0; nt < 8; nt++) {
            int c = wn * 64 + nt * 8 + 2 * tig;
            if (r0 < M) {
                __half2 o = __floats2half2_rn(acc[mt][nt][0], acc[mt][nt][1]);
                *reinterpret_cast<__half2*>(C + (size_t)r0 * 128 + c) = o;
            }
            if (r1 < M) {
                __half2 o = __floats2half2_rn(acc[mt][nt][2], acc[mt][nt][3]);
                *reinterpret_cast<__half2*>(C + (size_t)r1 * 128 + c) = o;
            }
        }
    }
#undef LD_A
#undef ST_A
#undef CP_B
}

// ---------------- CSR SpMM (fp16 gather, fp32 accum, templated output) ----------------
template<typename OutT, bool RELU>
__global__ void spmm_csr_kernel(const __half* __restrict__ T, const int* __restrict__ csr,
                                const int* __restrict__ roff, const float* __restrict__ csrc,
                                const float* __restrict__ cdst,
                                const float* __restrict__ bias, OutT* __restrict__ out, int n) {
    int w    = (blockIdx.x * blockDim.x + threadIdx.x) >> 5;
    int lane = threadIdx.x & 31;
    if (w >= n) return;
    int beg = __ldg(roff + w), end = __ldg(roff + w + 1);

    float4 acc = make_float4(0.f, 0.f, 0.f, 0.f);
    int i = beg;
    for (; i + 4 <= end; i += 4) {
        int s0 = __ldg(csr + i);
        int s1 = __ldg(csr + i + 1);
        int s2 = __ldg(csr + i + 2);
        int s3 = __ldg(csr + i + 3);
        float c0 = __ldg(csrc + s0);
        float c1 = __ldg(csrc + s1);
        float c2 = __ldg(csrc + s2);
        float c3 = __ldg(csrc + s3);
        uint2 u0 = *(reinterpret_cast<const uint2*>(T + (size_t)s0 * 128) + lane);
        uint2 u1 = *(reinterpret_cast<const uint2*>(T + (size_t)s1 * 128) + lane);
        uint2 u2 = *(reinterpret_cast<const uint2*>(T + (size_t)s2 * 128) + lane);
        uint2 u3 = *(reinterpret_cast<const uint2*>(T + (size_t)s3 * 128) + lane);
        float2 a0 = __half22float2(*reinterpret_cast<__half2*>(&u0.x));
        float2 b0v = __half22float2(*reinterpret_cast<__half2*>(&u0.y));
        float2 a1 = __half22float2(*reinterpret_cast<__half2*>(&u1.x));
        float2 b1v = __half22float2(*reinterpret_cast<__half2*>(&u1.y));
        float2 a2 = __half22float2(*reinterpret_cast<__half2*>(&u2.x));
        float2 b2v = __half22float2(*reinterpret_cast<__half2*>(&u2.y));
        float2 a3 = __half22float2(*reinterpret_cast<__half2*>(&u3.x));
        float2 b3v = __half22float2(*reinterpret_cast<__half2*>(&u3.y));
        acc.x += (a0.x * c0 + a1.x * c1) + (a2.x * c2 + a3.x * c3);
        acc.y += (a0.y * c0 + a1.y * c1) + (a2.y * c2 + a3.y * c3);
        acc.z += (b0v.x * c0 + b1v.x * c1) + (b2v.x * c2 + b3v.x * c3);
        acc.w += (b0v.y * c0 + b1v.y * c1) + (b2v.y * c2 + b3v.y * c3);
    }
    for (; i < end; i++) {
        int s = __ldg(csr + i);
        float c = __ldg(csrc + s);
        uint2 u = *(reinterpret_cast<const uint2*>(T + (size_t)s * 128) + lane);
        float2 a = __half22float2(*reinterpret_cast<__half2*>(&u.x));
        float2 b = __half22float2(*reinterpret_cast<__half2*>(&u.y));
        acc.x += a.x * c; acc.y += a.y * c; acc.z += b.x * c; acc.w += b.y * c;
    }
    float c = __ldg(cdst + w);
    float4 b = *reinterpret_cast<const float4*>(bias + (lane << 2));
    acc.x = acc.x * c + b.x;
    acc.y = acc.y * c + b.y;
    acc.z = acc.z * c + b.z;
    acc.w = acc.w * c + b.w;
    if (RELU) {
        acc.x = fmaxf(acc.x, 0.f); acc.y = fmaxf(acc.y, 0.f);
        acc.z = fmaxf(acc.z, 0.f); acc.w = fmaxf(acc.w, 0.f);
    }
    if (sizeof(OutT) == 2) {
        __half2 o0 = __floats2half2_rn(acc.x, acc.y);
        __half2 o1 = __floats2half2_rn(acc.z, acc.w);
        uint2 u = make_uint2(*reinterpret_cast<uint32_t*>(&o0),
                             *reinterpret_cast<uint32_t*>(&o1));
        *reinterpret_cast<uint2*>(reinterpret_cast<__half*>(out) + (size_t)w * 128 + (lane << 2)) = u;
    } else {
        *reinterpret_cast<float4*>(reinterpret_cast<float*>(out) + (size_t)w * 128 + (lane << 2)) = acc;
    }
}

// ---------------- final: logits = relu(h) @ Wc + bc ----------------
__global__ void final_kernel(const float* __restrict__ h, const float* __restrict__ Wc,
                             const float* __restrict__ bc, float* __restrict__ out_logits, int n) {
    __shared__ float hs[32][HID + 1];
    __shared__ float Wcs[HID][CLS];
    __shared__ float bcs[CLS];

    const int tid = threadIdx.x;
    const int n0  = blockIdx.x * 32;

    for (int i = tid; i < HID * CLS; i += 256) Wcs[i / CLS][i % CLS] = Wc[i];
    if (tid < CLS) bcs[tid] = bc[tid];

    for (int i = tid; i < 32 * HID; i += 256) {
        int r = i >> 7, c = i & 127;
        int g = n0 + r;
        hs[r][c] = (g < n) ? fmaxf(h[(size_t)g * HID + c], 0.f) : 0.f;
    }
    __syncthreads();

    int r  = tid & 31;
    int cg = tid >> 5;
    int g  = n0 + r;
    if (g < n) {
        float acc[5];
#pragma unroll
        for (int j = 0; j < 5; j++) acc[j] = bcs[cg * 5 + j];
        for (int k = 0; k < HID; k++) {
            float a = hs[r][k];
#pragma unroll
            for (int j = 0; j < 5; j++) acc[j] = fmaf(a, Wcs[k][cg * 5 + j], acc[j]);
        }
#pragma unroll
        for (int j = 0; j < 5; j++) out_logits[(size_t)g * CLS + cg * 5 + j] = acc[j];
    }
}

// ---------------- launch ----------------
extern "C" void kernel_launch(void* const* d_in, const int* in_sizes, int n_in,
                              void* d_out, int out_size) {
    const float* x   = (const float*)d_in[0];
    const int*   src = (const int*)d_in[1];
    const int*   dst = (const int*)d_in[2];
    const float* W0  = (const float*)d_in[3];
    const float* b0  = (const float*)d_in[4];
    const float* W1  = (const float*)d_in[5];
    const float* b1  = (const float*)d_in[6];
    const float* Wc  = (const float*)d_in[7];
    const float* bc  = (const float*)d_in[8];

    const int n = in_sizes[0] / 256;
    const int e = in_sizes[1];

    int *ideg_s, *ideg_d, *roff, *cursor, *bsums, *csr;
    float *csrc, *cdst;
    __half *tmp, *hbuf;
    uint32_t *whi0, *wlo0, *whi1, *wlo1;
    cudaGetSymbolAddress((void**)&ideg_s, g_ideg_src);
    cudaGetSymbolAddress((void**)&ideg_d, g_ideg_dst);
    cudaGetSymbolAddress((void**)&roff,   g_roff);
    cudaGetSymbolAddress((void**)&cursor, g_cursor);
    cudaGetSymbolAddress((void**)&bsums,  g_bsums);
    cudaGetSymbolAddress((void**)&csr,    g_csr);
    cudaGetSymbolAddress((void**)&csrc,   g_csrc);
    cudaGetSymbolAddress((void**)&cdst,   g_cdst);
    cudaGetSymbolAddress((void**)&tmp,    g_tmp);
    cudaGetSymbolAddress((void**)&hbuf,   g_hbuf);
    cudaGetSymbolAddress((void**)&whi0,   g_whi0);
    cudaGetSymbolAddress((void**)&wlo0,   g_wlo0);
    cudaGetSymbolAddress((void**)&whi1,   g_whi1);
    cudaGetSymbolAddress((void**)&wlo1,   g_wlo1);

    float* out_h      = (float*)d_out;
    float* out_logits = out_h + (size_t)n * HID;

    static cudaStream_t s_side = nullptr;
    static cudaEvent_t  ev_fork = nullptr, ev_join = nullptr;
    if (s_side == nullptr) {
        cudaStreamCreateWithFlags(&s_side, cudaStreamNonBlocking);
        cudaEventCreateWithFlags(&ev_fork, cudaEventDisableTiming);
        cudaEventCreateWithFlags(&ev_join, cudaEventDisableTiming);
        cudaFuncSetAttribute(gemm_bf16_kernel<float>,
                             cudaFuncAttributeMaxDynamicSharedMemorySize, GEMM_SMEM);
        cudaFuncSetAttribute(gemm_bf16_kernel<__half>,
                             cudaFuncAttributeMaxDynamicSharedMemorySize, GEMM_SMEM);
    }

    const int nb = (n + 1023) / 1024;
    const int gblocks = (n + 127) / 128;
    const int sblocks = (int)(((size_t)n * 32 + 255) / 256);

    // ---- fork: CSR/degree chain on side stream; weight splits + GEMM1 on main ----
    cudaEventRecord(ev_fork, 0);
    cudaStreamWaitEvent(s_side, ev_fork, 0);

    zero_int2_kernel<<<(n + 255) / 256, 256, 0, s_side>>>(ideg_s, ideg_d, n);
    degree_kernel<<<(e + 255) / 256, 256, 0, s_side>>>(src, dst, e);
    scan1_kernel<<<nb, 1024, 0, s_side>>>(ideg_d, roff, bsums, n);
    scan2_kernel<<<1, 128, 0, s_side>>>(bsums, nb);
    scan3_kernel<<<(n + 255) / 256, 256, 0, s_side>>>(roff, cursor, bsums, n, e);
    csr_fill_kernel<<<(e + 255) / 256, 256, 0, s_side>>>(src, dst, cursor, csr, e);

    wsplit_kernel<<<64, 256>>>(W0, whi0, wlo0, 128);
    wsplit_kernel<<<32, 256>>>(W1, whi1, wlo1, 64);
    gemm_bf16_kernel<float><<<gblocks, 256, GEMM_SMEM>>>(x, whi0, wlo0, tmp, n, 256);

    // ---- join ----
    cudaEventRecord(ev_join, s_side);
    cudaStreamWaitEvent(0, ev_join, 0);

    spmm_csr_kernel<__half, true><<<sblocks, 256>>>(tmp, csr, roff, csrc, cdst, b0, hbuf, n);

    gemm_bf16_kernel<__half><<<gblocks, 256, GEMM_SMEM>>>(hbuf, whi1, wlo1, tmp, n, 128);
    spmm_csr_kernel<float, false><<<sblocks, 256>>>(tmp, csr, roff, csrc, cdst, b1, out_h, n);

    final_kernel<<<(n + 31) / 32, 256>>>(out_h, Wc, bc, out_logits, n);
}

// round 11
// speedup vs baseline: 1.1209x; 1.1209x over previous
#include <cuda_runtime.h>
#include <cuda_fp16.h>
#include <cstdint>

#define MAXN 100000
#define MAXE 1600000
#define HID 128
#define CLS 40

// ---------------- scratch (static device memory, no allocations) ----------------
__device__ int      g_ideg_src[MAXN];
__device__ int      g_ideg_dst[MAXN];
__device__ float    g_csrc[MAXN];
__device__ float    g_cdst[MAXN];
__device__ int      g_roff[MAXN + 1];
__device__ int      g_cursor[MAXN];
__device__ int      g_bsums[128];
__device__ int      g_csr[MAXE];
__device__ __half   g_tmp [(size_t)MAXN * HID];     // GEMM output, fp16
__device__ __half   g_hbuf[(size_t)MAXN * HID];     // layer-1 activations, fp16
// W packed fp16: [kpair][n 128] fp16x2 (k-pair per u32)
__device__ uint32_t g_w0[16384];                    // W0: 128 kp x 128
__device__ uint32_t g_w1[8192];                     // W1: 64 kp x 128

// ---------------- utilities ----------------
__global__ void zero_int2_kernel(int* __restrict__ a, int* __restrict__ b, int n) {
    int i = blockIdx.x * blockDim.x + threadIdx.x;
    if (i < n) { a[i] = 0; b[i] = 0; }
}

__global__ void degree_kernel(const int* __restrict__ src, const int* __restrict__ dst, int e) {
    int i = blockIdx.x * blockDim.x + threadIdx.x;
    if (i < e) {
        atomicAdd(&g_ideg_src[src[i]], 1);
        atomicAdd(&g_ideg_dst[dst[i]], 1);
    }
}

// ---------------- 3-phase exclusive scan of in-degrees -> CSR row offsets ----------------
__global__ void scan1_kernel(const int* __restrict__ deg, int* __restrict__ out,
                             int* __restrict__ bsums, int n) {
    __shared__ int sm[1024];
    int i = blockIdx.x * 1024 + threadIdx.x;
    int v = (i < n) ? deg[i] : 0;
    sm[threadIdx.x] = v;
    __syncthreads();
    for (int off = 1; off < 1024; off <<= 1) {
        int t = (threadIdx.x >= off) ? sm[threadIdx.x - off] : 0;
        __syncthreads();
        sm[threadIdx.x] += t;
        __syncthreads();
    }
    if (i < n) out[i] = sm[threadIdx.x] - v;
    if (threadIdx.x == 1023) bsums[blockIdx.x] = sm[1023];
}

__global__ void scan2_kernel(int* __restrict__ bsums, int nb) {
    __shared__ int sm[128];
    int t = threadIdx.x;
    int v = (t < nb) ? bsums[t] : 0;
    sm[t] = v;
    __syncthreads();
    for (int off = 1; off < 128; off <<= 1) {
        int u = (t >= off) ? sm[t - off] : 0;
        __syncthreads();
        sm[t] += u;
        __syncthreads();
    }
    if (t < nb) bsums[t] = sm[t] - v;
}

__global__ void scan3_kernel(int* __restrict__ roff, int* __restrict__ cursor,
                             const int* __restrict__ bsums, int n, int e) {
    int i = blockIdx.x * blockDim.x + threadIdx.x;
    if (i < n) {
        int v = roff[i] + bsums[i >> 10];
        roff[i] = v;
        cursor[i] = v;
        g_csrc[i] = rsqrtf(fmaxf((float)g_ideg_src[i], 1.f));
        g_cdst[i] = rsqrtf(fmaxf((float)g_ideg_dst[i], 1.f));
    }
    if (i == 0) roff[n] = e;
}

__global__ void csr_fill_kernel(const int* __restrict__ src, const int* __restrict__ dst,
                                int* __restrict__ cursor, int* __restrict__ csr, int e) {
    int i = blockIdx.x * blockDim.x + threadIdx.x;
    if (i < e) {
        int d = dst[i];
        int pos = atomicAdd(&cursor[d], 1);
        csr[pos] = src[i];
    }
}

// ---------------- weight pack: W[K,128] fp32 -> [kp][n] fp16x2 ----------------
__global__ void wpack_kernel(const float* __restrict__ W, uint32_t* __restrict__ wp, int kpairs) {
    int idx = blockIdx.x * blockDim.x + threadIdx.x;   // (kp, n)
    if (idx < kpairs * 128) {
        int kp = idx >> 7, n = idx & 127;
        float x = W[(size_t)(2 * kp) * 128 + n];
        float y = W[(size_t)(2 * kp + 1) * 128 + n];
        __half2 h = __floats2half2_rn(x, y);
        wp[idx] = *reinterpret_cast<uint32_t*>(&h);
    }
}

#define MMA_FP16(d, a, b0v, b1v)                                                  \
    asm volatile("mma.sync.aligned.m16n8k16.row.col.f32.f16.f16.f32 "             \
                 "{%0,%1,%2,%3}, {%4,%5,%6,%7}, {%8,%9}, {%0,%1,%2,%3};"          \
                 : "+f"((d)[0]), "+f"((d)[1]), "+f"((d)[2]), "+f"((d)[3])         \
                 : "r"((a)[0]), "r"((a)[1]), "r"((a)[2]), "r"((a)[3]),            \
                   "r"(b0v), "r"(b1v));

#define AS_STRIDE 20     // u32 per A row (16 kpairs + pad)
#define BS_STRIDE 136    // u32 per B kp row (128 + pad)
#define AS_BUF    2560   // 128 * AS_STRIDE
#define BS_BUF    2176   // 16 * BS_STRIDE
#define GEMM_SMEM ((AS_BUF*2 + BS_BUF*2) * 4)   // 37888 bytes

#define CP_ASYNC16(dst_u32, src_ptr)                                              \
    asm volatile("cp.async.cg.shared.global [%0], [%1], 16;"                      \
                 :: "r"(dst_u32), "l"(src_ptr))
#define CP_COMMIT() asm volatile("cp.async.commit_group;" ::: "memory")
#define CP_WAIT0()  asm volatile("cp.async.wait_group 0;"  ::: "memory")

__device__ __forceinline__ float4 ld4(const float* A, size_t off) {
    return __ldg(reinterpret_cast<const float4*>(A + off));
}
__device__ __forceinline__ float4 ld4(const __half* A, size_t off) {
    uint2 u = __ldg(reinterpret_cast<const uint2*>(A + off));
    float2 a = __half22float2(*reinterpret_cast<__half2*>(&u.x));
    float2 b = __half22float2(*reinterpret_cast<__half2*>(&u.y));
    return make_float4(a.x, a.y, b.x, b.y);
}

// ---------------- double-buffered fp16 HMMA GEMM: C(fp16) = A[M,K] @ Wpack ----
template<typename TA>
__global__ __launch_bounds__(256, 2)
void gemm_fp16_kernel(const TA* __restrict__ A, const uint32_t* __restrict__ wp,
                      __half* __restrict__ C, int M, int K) {
    extern __shared__ uint32_t smem[];
    uint32_t* As = smem;                 // [2][AS_BUF]
    uint32_t* Bs = smem + 2 * AS_BUF;    // [2][BS_BUF]

    const int tid  = threadIdx.x;
    const int warp = tid >> 5, lane = tid & 31;
    const int wm   = warp >> 1, wn = warp & 1;
    const int gid  = lane >> 2, tig = lane & 3;
    const int m0   = blockIdx.x * 128;
    const int nIter = K >> 5;

    float acc[2][8][4];
#pragma unroll
    for (int mt = 0; mt < 2; mt++)
#pragma unroll
        for (int nt = 0; nt < 8; nt++)
#pragma unroll
            for (int j = 0; j < 4; j++) acc[mt][nt][j] = 0.f;

    float4 aReg[4];

#define LD_A(k0)                                                                   \
    {                                                                              \
        _Pragma("unroll")                                                          \
        for (int l = 0; l < 4; l++) {                                              \
            int idx = tid + l * 256;                                               \
            int r = idx >> 3, c4 = idx & 7;                                        \
            aReg[l] = (m0 + r < M)                                                 \
                ? ld4(A, (size_t)(m0 + r) * K + (k0) + (c4 << 2))                  \
                : make_float4(0.f, 0.f, 0.f, 0.f);                                 \
        }                                                                          \
    }

#define ST_A(dst)                                                                  \
    {                                                                              \
        _Pragma("unroll")                                                          \
        for (int l = 0; l < 4; l++) {                                              \
            int idx = tid + l * 256;                                               \
            int r = idx >> 3, c4 = idx & 7;                                        \
            __half2 h0 = __floats2half2_rn(aReg[l].x, aReg[l].y);                  \
            __half2 h1 = __floats2half2_rn(aReg[l].z, aReg[l].w);                  \
            (dst)[r * AS_STRIDE + 2 * c4]     = *reinterpret_cast<uint32_t*>(&h0); \
            (dst)[r * AS_STRIDE + 2 * c4 + 1] = *reinterpret_cast<uint32_t*>(&h1); \
        }                                                                          \
    }

#define CP_B(k0p, dst)                                                             \
    {                                                                              \
        _Pragma("unroll")                                                          \
        for (int l = 0; l < 2; l++) {                                              \
            int idx = tid + l * 256;                                               \
            int kp = idx >> 5, n16 = idx & 31;                                     \
            uint32_t dh = (uint32_t)__cvta_generic_to_shared((dst) + kp * BS_STRIDE + n16 * 4); \
            CP_ASYNC16(dh, wp + ((k0p) + kp) * 128 + n16 * 4);                     \
        }                                                                          \
    }

    // prologue
    CP_B(0, Bs);
    CP_COMMIT();
    LD_A(0);
    ST_A(As);
    CP_WAIT0();
    __syncthreads();

    for (int it = 0; it < nIter; it++) {
        const int cur = it & 1, nxt = cur ^ 1;
        const bool more = (it + 1 < nIter);
        if (more) {
            LD_A((it + 1) << 5);
            CP_B((it + 1) << 4, Bs + nxt * BS_BUF);
            CP_COMMIT();
        }

        const uint32_t* aC = As + cur * AS_BUF;
        const uint32_t* bC = Bs + cur * BS_BUF;

#pragma unroll
        for (int kkp = 0; kkp < 16; kkp += 8) {
            uint32_t a[2][4];
#pragma unroll
            for (int mt = 0; mt < 2; mt++) {
                int rb = wm * 32 + mt * 16 + gid;
                int p0 = kkp + tig;
                a[mt][0] = aC[rb * AS_STRIDE + p0];
                a[mt][1] = aC[(rb + 8) * AS_STRIDE + p0];
                a[mt][2] = aC[rb * AS_STRIDE + p0 + 4];
                a[mt][3] = aC[(rb + 8) * AS_STRIDE + p0 + 4];
            }
#pragma unroll
            for (int nt = 0; nt < 8; nt++) {
                int cb = wn * 64 + nt * 8 + gid;
                uint32_t b0 = bC[(kkp + tig)     * BS_STRIDE + cb];
                uint32_t b1 = bC[(kkp + tig + 4) * BS_STRIDE + cb];
#pragma unroll
                for (int mt = 0; mt < 2; mt++) {
                    MMA_FP16(acc[mt][nt], a[mt], b0, b1);
                }
            }
        }

        if (more) {
            ST_A(As + nxt * AS_BUF);
            CP_WAIT0();
        }
        __syncthreads();
    }

    // epilogue: store fp16 pairs (c_src applied later in SpMM gather)
#pragma unroll
    for (int mt = 0; mt < 2; mt++) {
        int r0 = m0 + wm * 32 + mt * 16 + gid;
        int r1 = r0 + 8;
#pragma unroll
        for (int nt = 0; nt < 8; nt++) {
            int c = wn * 64 + nt * 8 + 2 * tig;
            if (r0 < M) {
                __half2 o = __floats2half2_rn(acc[mt][nt][0], acc[mt][nt][1]);
                *reinterpret_cast<__half2*>(C + (size_t)r0 * 128 + c) = o;
            }
            if (r1 < M) {
                __half2 o = __floats2half2_rn(acc[mt][nt][2], acc[mt][nt][3]);
                *reinterpret_cast<__half2*>(C + (size_t)r1 * 128 + c) = o;
            }
        }
    }
#undef LD_A
#undef ST_A
#undef CP_B
}

// ---------------- CSR SpMM (fp16 gather, fp32 accum, templated output) ----------------
template<typename OutT, bool RELU>
__global__ void spmm_csr_kernel(const __half* __restrict__ T, const int* __restrict__ csr,
                                const int* __restrict__ roff, const float* __restrict__ csrc,
                                const float* __restrict__ cdst,
                                const float* __restrict__ bias, OutT* __restrict__ out, int n) {
    int w    = (blockIdx.x * blockDim.x + threadIdx.x) >> 5;
    int lane = threadIdx.x & 31;
    if (w >= n) return;
    int beg = __ldg(roff + w), end = __ldg(roff + w + 1);

    float4 acc = make_float4(0.f, 0.f, 0.f, 0.f);
    int i = beg;
    for (; i + 4 <= end; i += 4) {
        int s0 = __ldg(csr + i);
        int s1 = __ldg(csr + i + 1);
        int s2 = __ldg(csr + i + 2);
        int s3 = __ldg(csr + i + 3);
        float c0 = __ldg(csrc + s0);
        float c1 = __ldg(csrc + s1);
        float c2 = __ldg(csrc + s2);
        float c3 = __ldg(csrc + s3);
        uint2 u0 = *(reinterpret_cast<const uint2*>(T + (size_t)s0 * 128) + lane);
        uint2 u1 = *(reinterpret_cast<const uint2*>(T + (size_t)s1 * 128) + lane);
        uint2 u2 = *(reinterpret_cast<const uint2*>(T + (size_t)s2 * 128) + lane);
        uint2 u3 = *(reinterpret_cast<const uint2*>(T + (size_t)s3 * 128) + lane);
        float2 a0 = __half22float2(*reinterpret_cast<__half2*>(&u0.x));
        float2 b0v = __half22float2(*reinterpret_cast<__half2*>(&u0.y));
        float2 a1 = __half22float2(*reinterpret_cast<__half2*>(&u1.x));
        float2 b1v = __half22float2(*reinterpret_cast<__half2*>(&u1.y));
        float2 a2 = __half22float2(*reinterpret_cast<__half2*>(&u2.x));
        float2 b2v = __half22float2(*reinterpret_cast<__half2*>(&u2.y));
        float2 a3 = __half22float2(*reinterpret_cast<__half2*>(&u3.x));
        float2 b3v = __half22float2(*reinterpret_cast<__half2*>(&u3.y));
        acc.x += (a0.x * c0 + a1.x * c1) + (a2.x * c2 + a3.x * c3);
        acc.y += (a0.y * c0 + a1.y * c1) + (a2.y * c2 + a3.y * c3);
        acc.z += (b0v.x * c0 + b1v.x * c1) + (b2v.x * c2 + b3v.x * c3);
        acc.w += (b0v.y * c0 + b1v.y * c1) + (b2v.y * c2 + b3v.y * c3);
    }
    for (; i < end; i++) {
        int s = __ldg(csr + i);
        float c = __ldg(csrc + s);
        uint2 u = *(reinterpret_cast<const uint2*>(T + (size_t)s * 128) + lane);
        float2 a = __half22float2(*reinterpret_cast<__half2*>(&u.x));
        float2 b = __half22float2(*reinterpret_cast<__half2*>(&u.y));
        acc.x += a.x * c; acc.y += a.y * c; acc.z += b.x * c; acc.w += b.y * c;
    }
    float c = __ldg(cdst + w);
    float4 b = *reinterpret_cast<const float4*>(bias + (lane << 2));
    acc.x = acc.x * c + b.x;
    acc.y = acc.y * c + b.y;
    acc.z = acc.z * c + b.z;
    acc.w = acc.w * c + b.w;
    if (RELU) {
        acc.x = fmaxf(acc.x, 0.f); acc.y = fmaxf(acc.y, 0.f);
        acc.z = fmaxf(acc.z, 0.f); acc.w = fmaxf(acc.w, 0.f);
    }
    if (sizeof(OutT) == 2) {
        __half2 o0 = __floats2half2_rn(acc.x, acc.y);
        __half2 o1 = __floats2half2_rn(acc.z, acc.w);
        uint2 u = make_uint2(*reinterpret_cast<uint32_t*>(&o0),
                             *reinterpret_cast<uint32_t*>(&o1));
        *reinterpret_cast<uint2*>(reinterpret_cast<__half*>(out) + (size_t)w * 128 + (lane << 2)) = u;
    } else {
        *reinterpret_cast<float4*>(reinterpret_cast<float*>(out) + (size_t)w * 128 + (lane << 2)) = acc;
    }
}

// ---------------- final: logits = relu(h) @ Wc + bc ----------------
__global__ void final_kernel(const float* __restrict__ h, const float* __restrict__ Wc,
                             const float* __restrict__ bc, float* __restrict__ out_logits, int n) {
    __shared__ float hs[32][HID + 1];
    __shared__ float Wcs[HID][CLS];
    __shared__ float bcs[CLS];

    const int tid = threadIdx.x;
    const int n0  = blockIdx.x * 32;

    for (int i = tid; i < HID * CLS; i += 256) Wcs[i / CLS][i % CLS] = Wc[i];
    if (tid < CLS) bcs[tid] = bc[tid];

    for (int i = tid; i < 32 * HID; i += 256) {
        int r = i >> 7, c = i & 127;
        int g = n0 + r;
        hs[r][c] = (g < n) ? fmaxf(h[(size_t)g * HID + c], 0.f) : 0.f;
    }
    __syncthreads();

    int r  = tid & 31;
    int cg = tid >> 5;
    int g  = n0 + r;
    if (g < n) {
        float acc[5];
#pragma unroll
        for (int j = 0; j < 5; j++) acc[j] = bcs[cg * 5 + j];
        for (int k = 0; k < HID; k++) {
            float a = hs[r][k];
#pragma unroll
            for (int j = 0; j < 5; j++) acc[j] = fmaf(a, Wcs[k][cg * 5 + j], acc[j]);
        }
#pragma unroll
        for (int j = 0; j < 5; j++) out_logits[(size_t)g * CLS + cg * 5 + j] = acc[j];
    }
}

// ---------------- launch ----------------
extern "C" void kernel_launch(void* const* d_in, const int* in_sizes, int n_in,
                              void* d_out, int out_size) {
    const float* x   = (const float*)d_in[0];
    const int*   src = (const int*)d_in[1];
    const int*   dst = (const int*)d_in[2];
    const float* W0  = (const float*)d_in[3];
    const float* b0  = (const float*)d_in[4];
    const float* W1  = (const float*)d_in[5];
    const float* b1  = (const float*)d_in[6];
    const float* Wc  = (const float*)d_in[7];
    const float* bc  = (const float*)d_in[8];

    const int n = in_sizes[0] / 256;
    const int e = in_sizes[1];

    int *ideg_s, *ideg_d, *roff, *cursor, *bsums, *csr;
    float *csrc, *cdst;
    __half *tmp, *hbuf;
    uint32_t *w0, *w1;
    cudaGetSymbolAddress((void**)&ideg_s, g_ideg_src);
    cudaGetSymbolAddress((void**)&ideg_d, g_ideg_dst);
    cudaGetSymbolAddress((void**)&roff,   g_roff);
    cudaGetSymbolAddress((void**)&cursor, g_cursor);
    cudaGetSymbolAddress((void**)&bsums,  g_bsums);
    cudaGetSymbolAddress((void**)&csr,    g_csr);
    cudaGetSymbolAddress((void**)&csrc,   g_csrc);
    cudaGetSymbolAddress((void**)&cdst,   g_cdst);
    cudaGetSymbolAddress((void**)&tmp,    g_tmp);
    cudaGetSymbolAddress((void**)&hbuf,   g_hbuf);
    cudaGetSymbolAddress((void**)&w0,     g_w0);
    cudaGetSymbolAddress((void**)&w1,     g_w1);

    float* out_h      = (float*)d_out;
    float* out_logits = out_h + (size_t)n * HID;

    static cudaStream_t s_side = nullptr;
    static cudaEvent_t  ev_fork = nullptr, ev_join = nullptr;
    if (s_side == nullptr) {
        cudaStreamCreateWithFlags(&s_side, cudaStreamNonBlocking);
        cudaEventCreateWithFlags(&ev_fork, cudaEventDisableTiming);
        cudaEventCreateWithFlags(&ev_join, cudaEventDisableTiming);
        cudaFuncSetAttribute(gemm_fp16_kernel<float>,
                             cudaFuncAttributeMaxDynamicSharedMemorySize, GEMM_SMEM);
        cudaFuncSetAttribute(gemm_fp16_kernel<__half>,
                             cudaFuncAttributeMaxDynamicSharedMemorySize, GEMM_SMEM);
    }

    const int nb = (n + 1023) / 1024;
    const int gblocks = (n + 127) / 128;
    const int sblocks = (int)(((size_t)n * 32 + 255) / 256);

    // ---- fork: CSR/degree chain on side stream; weight packs + GEMM1 on main ----
    cudaEventRecord(ev_fork, 0);
    cudaStreamWaitEvent(s_side, ev_fork, 0);

    zero_int2_kernel<<<(n + 255) / 256, 256, 0, s_side>>>(ideg_s, ideg_d, n);
    degree_kernel<<<(e + 255) / 256, 256, 0, s_side>>>(src, dst, e);
    scan1_kernel<<<nb, 1024, 0, s_side>>>(ideg_d, roff, bsums, n);
    scan2_kernel<<<1, 128, 0, s_side>>>(bsums, nb);
    scan3_kernel<<<(n + 255) / 256, 256, 0, s_side>>>(roff, cursor, bsums, n, e);
    csr_fill_kernel<<<(e + 255) / 256, 256, 0, s_side>>>(src, dst, cursor, csr, e);

    wpack_kernel<<<64, 256>>>(W0, w0, 128);
    wpack_kernel<<<32, 256>>>(W1, w1, 64);
    gemm_fp16_kernel<float><<<gblocks, 256, GEMM_SMEM>>>(x, w0, tmp, n, 256);

    // ---- join ----
    cudaEventRecord(ev_join, s_side);
    cudaStreamWaitEvent(0, ev_join, 0);

    spmm_csr_kernel<__half, true><<<sblocks, 256>>>(tmp, csr, roff, csrc, cdst, b0, hbuf, n);

    gemm_fp16_kernel<__half><<<gblocks, 256, GEMM_SMEM>>>(hbuf, w1, tmp, n, 128);
    spmm_csr_kernel<float, false><<<sblocks, 256>>>(tmp, csr, roff, csrc, cdst, b1, out_h, n);

    final_kernel<<<(n + 31) / 32, 256>>>(out_h, Wc, bc, out_logits, n);
}

// round 12
// speedup vs baseline: 1.1621x; 1.0368x over previous
#include <cuda_runtime.h>
#include <cuda_fp16.h>
#include <cstdint>

#define MAXN 100000
#define MAXE 1600000
#define HID 128
#define CLS 40

// ---------------- scratch (static device memory, no allocations) ----------------
__device__ int      g_ideg_src[MAXN];
__device__ int      g_ideg_dst[MAXN];
__device__ float    g_csrc[MAXN];
__device__ float    g_cdst[MAXN];
__device__ int      g_roff[MAXN + 1];
__device__ int      g_cursor[MAXN];
__device__ int      g_bsums[128];
__device__ int      g_csr[MAXE];
__device__ __half   g_tmp [(size_t)MAXN * HID];     // GEMM output, fp16
__device__ __half   g_hbuf[(size_t)MAXN * HID];     // layer-1 activations, fp16
// W packed fp16: [kpair][n 128] fp16x2; w0 then w1 in one array
__device__ uint32_t g_w0[16384];                    // W0: 128 kp x 128
__device__ uint32_t g_w1[8192];                     // W1: 64 kp x 128

// ---------------- utilities ----------------
__global__ void zero_int2_kernel(int* __restrict__ a, int* __restrict__ b, int n) {
    int i = blockIdx.x * blockDim.x + threadIdx.x;
    if (i < n) { a[i] = 0; b[i] = 0; }
}

__global__ void degree_kernel(const int* __restrict__ src, const int* __restrict__ dst, int e) {
    int i = blockIdx.x * blockDim.x + threadIdx.x;
    if (i < e) {
        atomicAdd(&g_ideg_src[src[i]], 1);
        atomicAdd(&g_ideg_dst[dst[i]], 1);
    }
}

// ---------------- 3-phase exclusive scan of in-degrees -> CSR row offsets ----------------
__global__ void scan1_kernel(const int* __restrict__ deg, int* __restrict__ out,
                             int* __restrict__ bsums, int n) {
    __shared__ int sm[1024];
    int i = blockIdx.x * 1024 + threadIdx.x;
    int v = (i < n) ? deg[i] : 0;
    sm[threadIdx.x] = v;
    __syncthreads();
    for (int off = 1; off < 1024; off <<= 1) {
        int t = (threadIdx.x >= off) ? sm[threadIdx.x - off] : 0;
        __syncthreads();
        sm[threadIdx.x] += t;
        __syncthreads();
    }
    if (i < n) out[i] = sm[threadIdx.x] - v;
    if (threadIdx.x == 1023) bsums[blockIdx.x] = sm[1023];
}

__global__ void scan2_kernel(int* __restrict__ bsums, int nb) {
    __shared__ int sm[128];
    int t = threadIdx.x;
    int v = (t < nb) ? bsums[t] : 0;
    sm[t] = v;
    __syncthreads();
    for (int off = 1; off < 128; off <<= 1) {
        int u = (t >= off) ? sm[t - off] : 0;
        __syncthreads();
        sm[t] += u;
        __syncthreads();
    }
    if (t < nb) bsums[t] = sm[t] - v;
}

__global__ void scan3_kernel(int* __restrict__ roff, int* __restrict__ cursor,
                             const int* __restrict__ bsums, int n, int e) {
    int i = blockIdx.x * blockDim.x + threadIdx.x;
    if (i < n) {
        int v = roff[i] + bsums[i >> 10];
        roff[i] = v;
        cursor[i] = v;
        g_csrc[i] = rsqrtf(fmaxf((float)g_ideg_src[i], 1.f));
        g_cdst[i] = rsqrtf(fmaxf((float)g_ideg_dst[i], 1.f));
    }
    if (i == 0) roff[n] = e;
}

__global__ void csr_fill_kernel(const int* __restrict__ src, const int* __restrict__ dst,
                                int* __restrict__ cursor, int* __restrict__ csr, int e) {
    int i = blockIdx.x * blockDim.x + threadIdx.x;
    if (i < e) {
        int d = dst[i];
        int pos = atomicAdd(&cursor[d], 1);
        csr[pos] = src[i];
    }
}

// ---------------- weight pack (both layers in one launch) ----------------
__global__ void wpack_kernel(const float* __restrict__ W0, const float* __restrict__ W1) {
    int idx = blockIdx.x * blockDim.x + threadIdx.x;
    if (idx < 16384) {                       // W0: 128 kpairs
        int kp = idx >> 7, n = idx & 127;
        __half2 h = __floats2half2_rn(W0[(size_t)(2 * kp) * 128 + n],
                                      W0[(size_t)(2 * kp + 1) * 128 + n]);
        g_w0[idx] = *reinterpret_cast<uint32_t*>(&h);
    } else if (idx < 24576) {                // W1: 64 kpairs
        int j = idx - 16384;
        int kp = j >> 7, n = j & 127;
        __half2 h = __floats2half2_rn(W1[(size_t)(2 * kp) * 128 + n],
                                      W1[(size_t)(2 * kp + 1) * 128 + n]);
        g_w1[j] = *reinterpret_cast<uint32_t*>(&h);
    }
}

#define MMA_FP16(d, a, b0v, b1v)                                                  \
    asm volatile("mma.sync.aligned.m16n8k16.row.col.f32.f16.f16.f32 "             \
                 "{%0,%1,%2,%3}, {%4,%5,%6,%7}, {%8,%9}, {%0,%1,%2,%3};"          \
                 : "+f"((d)[0]), "+f"((d)[1]), "+f"((d)[2]), "+f"((d)[3])         \
                 : "r"((a)[0]), "r"((a)[1]), "r"((a)[2]), "r"((a)[3]),            \
                   "r"(b0v), "r"(b1v));

#define AS_STRIDE 20
#define BS_STRIDE 136
#define AS_BUF    2560
#define BS_BUF    2176
#define GEMM_SMEM ((AS_BUF*2 + BS_BUF*2) * 4)   // 37888 bytes

#define CP_ASYNC16(dst_u32, src_ptr)                                              \
    asm volatile("cp.async.cg.shared.global [%0], [%1], 16;"                      \
                 :: "r"(dst_u32), "l"(src_ptr))
#define CP_COMMIT() asm volatile("cp.async.commit_group;" ::: "memory")
#define CP_WAIT0()  asm volatile("cp.async.wait_group 0;"  ::: "memory")

__device__ __forceinline__ float4 ld4(const float* A, size_t off) {
    return __ldg(reinterpret_cast<const float4*>(A + off));
}
__device__ __forceinline__ float4 ld4(const __half* A, size_t off) {
    uint2 u = __ldg(reinterpret_cast<const uint2*>(A + off));
    float2 a = __half22float2(*reinterpret_cast<__half2*>(&u.x));
    float2 b = __half22float2(*reinterpret_cast<__half2*>(&u.y));
    return make_float4(a.x, a.y, b.x, b.y);
}

// ---------------- double-buffered fp16 HMMA GEMM: C(fp16) = (A[M,K] @ W) [* rs[m]] ----
template<typename TA, bool SCALE>
__global__ __launch_bounds__(256, 2)
void gemm_fp16_kernel(const TA* __restrict__ A, const uint32_t* __restrict__ wp,
                      const float* __restrict__ rs, __half* __restrict__ C, int M, int K) {
    extern __shared__ uint32_t smem[];
    uint32_t* As = smem;
    uint32_t* Bs = smem + 2 * AS_BUF;

    const int tid  = threadIdx.x;
    const int warp = tid >> 5, lane = tid & 31;
    const int wm   = warp >> 1, wn = warp & 1;
    const int gid  = lane >> 2, tig = lane & 3;
    const int m0   = blockIdx.x * 128;
    const int nIter = K >> 5;

    float acc[2][8][4];
#pragma unroll
    for (int mt = 0; mt < 2; mt++)
#pragma unroll
        for (int nt = 0; nt < 8; nt++)
#pragma unroll
            for (int j = 0; j < 4; j++) acc[mt][nt][j] = 0.f;

    float4 aReg[4];

#define LD_A(k0)                                                                   \
    {                                                                              \
        _Pragma("unroll")                                                          \
        for (int l = 0; l < 4; l++) {                                              \
            int idx = tid + l * 256;                                               \
            int r = idx >> 3, c4 = idx & 7;                                        \
            aReg[l] = (m0 + r < M)                                                 \
                ? ld4(A, (size_t)(m0 + r) * K + (k0) + (c4 << 2))                  \
                : make_float4(0.f, 0.f, 0.f, 0.f);                                 \
        }                                                                          \
    }

#define ST_A(dst)                                                                  \
    {                                                                              \
        _Pragma("unroll")                                                          \
        for (int l = 0; l < 4; l++) {                                              \
            int idx = tid + l * 256;                                               \
            int r = idx >> 3, c4 = idx & 7;                                        \
            __half2 h0 = __floats2half2_rn(aReg[l].x, aReg[l].y);                  \
            __half2 h1 = __floats2half2_rn(aReg[l].z, aReg[l].w);                  \
            (dst)[r * AS_STRIDE + 2 * c4]     = *reinterpret_cast<uint32_t*>(&h0); \
            (dst)[r * AS_STRIDE + 2 * c4 + 1] = *reinterpret_cast<uint32_t*>(&h1); \
        }                                                                          \
    }

#define CP_B(k0p, dst)                                                             \
    {                                                                              \
        _Pragma("unroll")                                                          \
        for (int l = 0; l < 2; l++) {                                              \
            int idx = tid + l * 256;                                               \
            int kp = idx >> 5, n16 = idx & 31;                                     \
            uint32_t dh = (uint32_t)__cvta_generic_to_shared((dst) + kp * BS_STRIDE + n16 * 4); \
            CP_ASYNC16(dh, wp + ((k0p) + kp) * 128 + n16 * 4);                     \
        }                                                                          \
    }

    CP_B(0, Bs);
    CP_COMMIT();
    LD_A(0);
    ST_A(As);
    CP_WAIT0();
    __syncthreads();

    for (int it = 0; it < nIter; it++) {
        const int cur = it & 1, nxt = cur ^ 1;
        const bool more = (it + 1 < nIter);
        if (more) {
            LD_A((it + 1) << 5);
            CP_B((it + 1) << 4, Bs + nxt * BS_BUF);
            CP_COMMIT();
        }

        const uint32_t* aC = As + cur * AS_BUF;
        const uint32_t* bC = Bs + cur * BS_BUF;

#pragma unroll
        for (int kkp = 0; kkp < 16; kkp += 8) {
            uint32_t a[2][4];
#pragma unroll
            for (int mt = 0; mt < 2; mt++) {
                int rb = wm * 32 + mt * 16 + gid;
                int p0 = kkp + tig;
                a[mt][0] = aC[rb * AS_STRIDE + p0];
                a[mt][1] = aC[(rb + 8) * AS_STRIDE + p0];
                a[mt][2] = aC[rb * AS_STRIDE + p0 + 4];
                a[mt][3] = aC[(rb + 8) * AS_STRIDE + p0 + 4];
            }
#pragma unroll
            for (int nt = 0; nt < 8; nt++) {
                int cb = wn * 64 + nt * 8 + gid;
                uint32_t b0 = bC[(kkp + tig)     * BS_STRIDE + cb];
                uint32_t b1 = bC[(kkp + tig + 4) * BS_STRIDE + cb];
#pragma unroll
                for (int mt = 0; mt < 2; mt++) {
                    MMA_FP16(acc[mt][nt], a[mt], b0, b1);
                }
            }
        }

        if (more) {
            ST_A(As + nxt * AS_BUF);
            CP_WAIT0();
        }
        __syncthreads();
    }

    // epilogue: optional row scale, store fp16 pairs
#pragma unroll
    for (int mt = 0; mt < 2; mt++) {
        int r0 = m0 + wm * 32 + mt * 16 + gid;
        int r1 = r0 + 8;
        float s0 = 1.f, s1 = 1.f;
        if (SCALE) {
            if (r0 < M) s0 = __ldg(rs + r0);
            if (r1 < M) s1 = __ldg(rs + r1);
        }
#pragma unroll
        for (int nt = 0; nt < 8; nt++) {
            int c = wn * 64 + nt * 8 + 2 * tig;
            if (r0 < M) {
                __half2 o = __floats2half2_rn(acc[mt][nt][0] * s0, acc[mt][nt][1] * s0);
                *reinterpret_cast<__half2*>(C + (size_t)r0 * 128 + c) = o;
            }
            if (r1 < M) {
                __half2 o = __floats2half2_rn(acc[mt][nt][2] * s1, acc[mt][nt][3] * s1);
                *reinterpret_cast<__half2*>(C + (size_t)r1 * 128 + c) = o;
            }
        }
    }
#undef LD_A
#undef ST_A
#undef CP_B
}

// ---------------- CSR SpMM, split-warp: 16 lanes per row, 2 edges per LDG.128 ----
// out[v] = (sum_{s in N(v)} [c_src[s]] * T[s]) * c_dst[v] + b   (optional relu)
template<typename OutT, bool RELU, bool SRC_SCALE>
__global__ void spmm_csr_kernel(const __half* __restrict__ T, const int* __restrict__ csr,
                                const int* __restrict__ roff, const float* __restrict__ csrc,
                                const float* __restrict__ cdst,
                                const float* __restrict__ bias, OutT* __restrict__ out, int n) {
    int w    = (blockIdx.x * blockDim.x + threadIdx.x) >> 5;
    int lane = threadIdx.x & 31;
    if (w >= n) return;
    const int half = lane >> 4;         // which edge of the pair
    const int fl   = lane & 15;         // feature lane: feats [fl*8, fl*8+8)
    int beg = __ldg(roff + w), end = __ldg(roff + w + 1);

    float acc[8];
#pragma unroll
    for (int j = 0; j < 8; j++) acc[j] = 0.f;

    int i = beg;
    for (; i + 4 <= end; i += 4) {
        int s0 = __ldg(csr + i + half);
        int s1 = __ldg(csr + i + 2 + half);
        float c0 = SRC_SCALE ? __ldg(csrc + s0) : 1.f;
        float c1 = SRC_SCALE ? __ldg(csrc + s1) : 1.f;
        uint4 v0 = *(reinterpret_cast<const uint4*>(T + (size_t)s0 * 128) + fl);
        uint4 v1 = *(reinterpret_cast<const uint4*>(T + (size_t)s1 * 128) + fl);
        {
            float2 p0 = __half22float2(*reinterpret_cast<__half2*>(&v0.x));
            float2 p1 = __half22float2(*reinterpret_cast<__half2*>(&v0.y));
            float2 p2 = __half22float2(*reinterpret_cast<__half2*>(&v0.z));
            float2 p3 = __half22float2(*reinterpret_cast<__half2*>(&v0.w));
            acc[0] += p0.x * c0; acc[1] += p0.y * c0;
            acc[2] += p1.x * c0; acc[3] += p1.y * c0;
            acc[4] += p2.x * c0; acc[5] += p2.y * c0;
            acc[6] += p3.x * c0; acc[7] += p3.y * c0;
        }
        {
            float2 p0 = __half22float2(*reinterpret_cast<__half2*>(&v1.x));
            float2 p1 = __half22float2(*reinterpret_cast<__half2*>(&v1.y));
            float2 p2 = __half22float2(*reinterpret_cast<__half2*>(&v1.z));
            float2 p3 = __half22float2(*reinterpret_cast<__half2*>(&v1.w));
            acc[0] += p0.x * c1; acc[1] += p0.y * c1;
            acc[2] += p1.x * c1; acc[3] += p1.y * c1;
            acc[4] += p2.x * c1; acc[5] += p2.y * c1;
            acc[6] += p3.x * c1; acc[7] += p3.y * c1;
        }
    }
    // pairwise remainder: each half handles edge i+half if in range
    for (; i < end; i += 2) {
        int e2 = i + half;
        if (e2 < end) {
            int s = __ldg(csr + e2);
            float c = SRC_SCALE ? __ldg(csrc + s) : 1.f;
            uint4 v = *(reinterpret_cast<const uint4*>(T + (size_t)s * 128) + fl);
            float2 p0 = __half22float2(*reinterpret_cast<__half2*>(&v.x));
            float2 p1 = __half22float2(*reinterpret_cast<__half2*>(&v.y));
            float2 p2 = __half22float2(*reinterpret_cast<__half2*>(&v.z));
            float2 p3 = __half22float2(*reinterpret_cast<__half2*>(&v.w));
            acc[0] += p0.x * c; acc[1] += p0.y * c;
            acc[2] += p1.x * c; acc[3] += p1.y * c;
            acc[4] += p2.x * c; acc[5] += p2.y * c;
            acc[6] += p3.x * c; acc[7] += p3.y * c;
        }
    }
    // cross-half reduce: lane l + lane l^16 hold partials of the same 8 feats
#pragma unroll
    for (int j = 0; j < 8; j++)
        acc[j] += __shfl_xor_sync(0xffffffffu, acc[j], 16);

    float c = __ldg(cdst + w);
    if (half == 0) {
        float4 b0 = *(reinterpret_cast<const float4*>(bias) + 2 * fl);
        float4 b1 = *(reinterpret_cast<const float4*>(bias) + 2 * fl + 1);
        float r0 = acc[0] * c + b0.x, r1 = acc[1] * c + b0.y;
        float r2 = acc[2] * c + b0.z, r3 = acc[3] * c + b0.w;
        float r4 = acc[4] * c + b1.x, r5 = acc[5] * c + b1.y;
        float r6 = acc[6] * c + b1.z, r7 = acc[7] * c + b1.w;
        if (RELU) {
            r0 = fmaxf(r0, 0.f); r1 = fmaxf(r1, 0.f); r2 = fmaxf(r2, 0.f); r3 = fmaxf(r3, 0.f);
            r4 = fmaxf(r4, 0.f); r5 = fmaxf(r5, 0.f); r6 = fmaxf(r6, 0.f); r7 = fmaxf(r7, 0.f);
        }
        if (sizeof(OutT) == 2) {
            __half2 h0 = __floats2half2_rn(r0, r1);
            __half2 h1 = __floats2half2_rn(r2, r3);
            __half2 h2 = __floats2half2_rn(r4, r5);
            __half2 h3 = __floats2half2_rn(r6, r7);
            uint4 u = make_uint4(*reinterpret_cast<uint32_t*>(&h0),
                                 *reinterpret_cast<uint32_t*>(&h1),
                                 *reinterpret_cast<uint32_t*>(&h2),
                                 *reinterpret_cast<uint32_t*>(&h3));
            *(reinterpret_cast<uint4*>(reinterpret_cast<__half*>(out) + (size_t)w * 128) + fl) = u;
        } else {
            float* o = reinterpret_cast<float*>(out) + (size_t)w * 128 + fl * 8;
            *reinterpret_cast<float4*>(o)     = make_float4(r0, r1, r2, r3);
            *reinterpret_cast<float4*>(o + 4) = make_float4(r4, r5, r6, r7);
        }
    }
}

// ---------------- final: logits = relu(h) @ Wc + bc ----------------
__global__ void final_kernel(const float* __restrict__ h, const float* __restrict__ Wc,
                             const float* __restrict__ bc, float* __restrict__ out_logits, int n) {
    __shared__ float hs[32][HID + 1];
    __shared__ float Wcs[HID][CLS];
    __shared__ float bcs[CLS];

    const int tid = threadIdx.x;
    const int n0  = blockIdx.x * 32;

    for (int i = tid; i < HID * CLS; i += 256) Wcs[i / CLS][i % CLS] = Wc[i];
    if (tid < CLS) bcs[tid] = bc[tid];

    for (int i = tid; i < 32 * HID; i += 256) {
        int r = i >> 7, c = i & 127;
        int g = n0 + r;
        hs[r][c] = (g < n) ? fmaxf(h[(size_t)g * HID + c], 0.f) : 0.f;
    }
    __syncthreads();

    int r  = tid & 31;
    int cg = tid >> 5;
    int g  = n0 + r;
    if (g < n) {
        float acc[5];
#pragma unroll
        for (int j = 0; j < 5; j++) acc[j] = bcs[cg * 5 + j];
        for (int k = 0; k < HID; k++) {
            float a = hs[r][k];
#pragma unroll
            for (int j = 0; j < 5; j++) acc[j] = fmaf(a, Wcs[k][cg * 5 + j], acc[j]);
        }
#pragma unroll
        for (int j = 0; j < 5; j++) out_logits[(size_t)g * CLS + cg * 5 + j] = acc[j];
    }
}

// ---------------- launch ----------------
extern "C" void kernel_launch(void* const* d_in, const int* in_sizes, int n_in,
                              void* d_out, int out_size) {
    const float* x   = (const float*)d_in[0];
    const int*   src = (const int*)d_in[1];
    const int*   dst = (const int*)d_in[2];
    const float* W0  = (const float*)d_in[3];
    const float* b0  = (const float*)d_in[4];
    const float* W1  = (const float*)d_in[5];
    const float* b1  = (const float*)d_in[6];
    const float* Wc  = (const float*)d_in[7];
    const float* bc  = (const float*)d_in[8];

    const int n = in_sizes[0] / 256;
    const int e = in_sizes[1];

    int *ideg_s, *ideg_d, *roff, *cursor, *bsums, *csr;
    float *csrc, *cdst;
    __half *tmp, *hbuf;
    uint32_t *w0, *w1;
    cudaGetSymbolAddress((void**)&ideg_s, g_ideg_src);
    cudaGetSymbolAddress((void**)&ideg_d, g_ideg_dst);
    cudaGetSymbolAddress((void**)&roff,   g_roff);
    cudaGetSymbolAddress((void**)&cursor, g_cursor);
    cudaGetSymbolAddress((void**)&bsums,  g_bsums);
    cudaGetSymbolAddress((void**)&csr,    g_csr);
    cudaGetSymbolAddress((void**)&csrc,   g_csrc);
    cudaGetSymbolAddress((void**)&cdst,   g_cdst);
    cudaGetSymbolAddress((void**)&tmp,    g_tmp);
    cudaGetSymbolAddress((void**)&hbuf,   g_hbuf);
    cudaGetSymbolAddress((void**)&w0,     g_w0);
    cudaGetSymbolAddress((void**)&w1,     g_w1);

    float* out_h      = (float*)d_out;
    float* out_logits = out_h + (size_t)n * HID;

    static cudaStream_t s_side = nullptr;
    static cudaEvent_t  ev_fork = nullptr, ev_join = nullptr;
    if (s_side == nullptr) {
        cudaStreamCreateWithFlags(&s_side, cudaStreamNonBlocking);
        cudaEventCreateWithFlags(&ev_fork, cudaEventDisableTiming);
        cudaEventCreateWithFlags(&ev_join, cudaEventDisableTiming);
        cudaFuncSetAttribute((const void*)gemm_fp16_kernel<float, false>,
                             cudaFuncAttributeMaxDynamicSharedMemorySize, GEMM_SMEM);
        cudaFuncSetAttribute((const void*)gemm_fp16_kernel<__half, true>,
                             cudaFuncAttributeMaxDynamicSharedMemorySize, GEMM_SMEM);
    }

    const int nb = (n + 1023) / 1024;
    const int gblocks = (n + 127) / 128;
    const int sblocks = (int)(((size_t)n * 32 + 255) / 256);

    // ---- fork: CSR/degree chain on side stream; weight pack + GEMM1 on main ----
    cudaEventRecord(ev_fork, 0);
    cudaStreamWaitEvent(s_side, ev_fork, 0);

    zero_int2_kernel<<<(n + 255) / 256, 256, 0, s_side>>>(ideg_s, ideg_d, n);
    degree_kernel<<<(e + 255) / 256, 256, 0, s_side>>>(src, dst, e);
    scan1_kernel<<<nb, 1024, 0, s_side>>>(ideg_d, roff, bsums, n);
    scan2_kernel<<<1, 128, 0, s_side>>>(bsums, nb);
    scan3_kernel<<<(n + 255) / 256, 256, 0, s_side>>>(roff, cursor, bsums, n, e);
    csr_fill_kernel<<<(e + 255) / 256, 256, 0, s_side>>>(src, dst, cursor, csr, e);

    wpack_kernel<<<96, 256>>>(W0, W1);
    gemm_fp16_kernel<float, false><<<gblocks, 256, GEMM_SMEM>>>(x, w0, nullptr, tmp, n, 256);

    // ---- join ----
    cudaEventRecord(ev_join, s_side);
    cudaStreamWaitEvent(0, ev_join, 0);

    // layer 0 aggregate (+bias+relu); c_src gathered per edge
    spmm_csr_kernel<__half, true, true><<<sblocks, 256>>>(tmp, csr, roff, csrc, cdst, b0, hbuf, n);

    // layer 1: GEMM applies c_src[r] in epilogue -> spmm2 skips csrc gather
    gemm_fp16_kernel<__half, true><<<gblocks, 256, GEMM_SMEM>>>(hbuf, w1, csrc, tmp, n, 128);
    spmm_csr_kernel<float, false, false><<<sblocks, 256>>>(tmp, csr, roff, nullptr, cdst, b1, out_h, n);

    final_kernel<<<(n + 31) / 32, 256>>>(out_h, Wc, bc, out_logits, n);
}